// round 6
// baseline (speedup 1.0000x reference)
#include <cuda_runtime.h>
#include <cuda_bf16.h>
#include <cstdint>
#include <math.h>

#define DHEAD 128
#define BM 128            // q rows per CTA (8 warps x 16)
#define BN 32             // keys per tile
#define NTH 256

#define KFS 144           // K fragment stride (words/key): 144 % 32 == 16
#define VFS 48            // V fragment stride (words/d):    48 % 32 == 16

// smem word offsets (4B units)
#define OFF_QF 0
#define QF_WORDS (8*8*256)               // [warp][kbk][hi 128 | lo 128] = 16384
#define OFF_KF QF_WORDS                  // 16384
#define OFF_VF (OFF_KF + BN*KFS)         // 16384 + 4608 = 20992
#define SMEM_WORDS (OFF_VF + DHEAD*VFS)  // 20992 + 6144 = 27136 -> 108544 B

__device__ __forceinline__ uint32_t packbf2(float x, float y) {
    __nv_bfloat162 t = __floats2bfloat162_rn(x, y);
    return *(uint32_t*)&t;
}
__device__ __forceinline__ void hilo(float x, float& h, float& l) {
    __nv_bfloat16 hb = __float2bfloat16_rn(x);
    h = __bfloat162float(hb);
    l = x - h;
}
__device__ __forceinline__ void mma_bf16(float c[4],
    uint32_t a0, uint32_t a1, uint32_t a2, uint32_t a3,
    uint32_t b0, uint32_t b1)
{
    asm volatile("mma.sync.aligned.m16n8k16.row.col.f32.bf16.bf16.f32 "
        "{%0,%1,%2,%3}, {%4,%5,%6,%7}, {%8,%9}, {%0,%1,%2,%3};"
        : "+f"(c[0]), "+f"(c[1]), "+f"(c[2]), "+f"(c[3])
        : "r"(a0), "r"(a1), "r"(a2), "r"(a3), "r"(b0), "r"(b1));
}

__global__ __launch_bounds__(NTH, 2)
void attn_bf16v6_kernel(const float* __restrict__ qg,
                        const float* __restrict__ kg,
                        const float* __restrict__ vg,
                        const int*   __restrict__ vlen,
                        float*       __restrict__ outg,
                        int Qlen, int Klen)
{
    extern __shared__ uint32_t su[];
    uint32_t* QF = su + OFF_QF;
    uint32_t* KF = su + OFF_KF;
    uint32_t* VF = su + OFF_VF;

    const int b  = blockIdx.y;
    const int q0 = blockIdx.x * BM;
    const int tid  = threadIdx.x;
    const int w    = tid >> 5;
    const int lane = tid & 31;
    const int g    = lane >> 2;
    const int c    = lane & 3;

    const int vl = vlen[b];
    const int ntiles = (vl + BN - 1) / BN;

    const float* kb = kg + (long)b * Klen * DHEAD;
    const float* vb = vg + (long)b * Klen * DHEAD;

    // ---- Q fragments -> smem (warp-private; each lane re-reads its own words)
    const float scale = 0.08838834764831845f;  // 1/sqrt(128)
    const int r0 = q0 + 16 * w + g;
    const int r1 = r0 + 8;
    {
        const float* qr0 = qg + ((long)b * Qlen + r0) * DHEAD;
        const float* qr1 = qg + ((long)b * Qlen + r1) * DHEAD;
        #pragma unroll
        for (int kbk = 0; kbk < 8; kbk++) {
            int base = 16 * kbk + 2 * c;
            float h0,l0,h1,l1;
            uint4 qh, ql;
            hilo(qr0[base]     * scale, h0, l0);
            hilo(qr0[base + 1] * scale, h1, l1);
            qh.x = packbf2(h0, h1); ql.x = packbf2(l0, l1);
            hilo(qr1[base]     * scale, h0, l0);
            hilo(qr1[base + 1] * scale, h1, l1);
            qh.y = packbf2(h0, h1); ql.y = packbf2(l0, l1);
            hilo(qr0[base + 8] * scale, h0, l0);
            hilo(qr0[base + 9] * scale, h1, l1);
            qh.z = packbf2(h0, h1); ql.z = packbf2(l0, l1);
            hilo(qr1[base + 8] * scale, h0, l0);
            hilo(qr1[base + 9] * scale, h1, l1);
            qh.w = packbf2(h0, h1); ql.w = packbf2(l0, l1);
            uint32_t* qd = QF + (w * 8 + kbk) * 256 + lane * 4;
            *(uint4*)qd         = qh;
            *(uint4*)(qd + 128) = ql;
        }
    }

    float o[16][4];
    #pragma unroll
    for (int j = 0; j < 16; j++)
        #pragma unroll
        for (int i = 0; i < 4; i++) o[j][i] = 0.0f;
    float m0 = -3.0e38f, m1 = -3.0e38f, l0s = 0.0f, l1s = 0.0f;

    for (int t = 0; t < ntiles; t++) {
        const int kbase = t * BN;
        __syncthreads();   // previous tile's MMA reads of KF/VF done

        // ---- convert K: direct LDG fp32 -> fragment-order bf16 hi/lo
        {
            int key = tid >> 3;          // 32 keys, 8 threads each
            int kbk = tid & 7;           // each thread owns one k16 block (16 d)
            const float* src = kb + (long)(kbase + key) * DHEAD + kbk * 16;
            float hi[16], lo[16];
            #pragma unroll
            for (int i = 0; i < 4; i++) {
                float4 v = *(const float4*)(src + i * 4);
                hilo(v.x, hi[4*i+0], lo[4*i+0]);
                hilo(v.y, hi[4*i+1], lo[4*i+1]);
                hilo(v.z, hi[4*i+2], lo[4*i+2]);
                hilo(v.w, hi[4*i+3], lo[4*i+3]);
            }
            uint32_t* dst = KF + key * KFS + kbk * 16;
            int rot = kbk >> 1;          // address swizzle: conflict-free STS.128
            #pragma unroll
            for (int cc = 0; cc < 4; cc++) {
                uint4 wv;
                wv.x = packbf2(hi[2*cc],   hi[2*cc+1]);
                wv.y = packbf2(hi[2*cc+8], hi[2*cc+9]);
                wv.z = packbf2(lo[2*cc],   lo[2*cc+1]);
                wv.w = packbf2(lo[2*cc+8], lo[2*cc+9]);
                // fragment for column-group cc lives at rotated address:
                *(uint4*)(dst + 4 * ((cc + rot) & 3)) = wv;
            }
        }
        // ---- convert V: key-pair rows -> fragment-order words
        {
            int kp   = tid & 15;         // 16 key-pairs
            int dgrp = tid >> 4;         // 16 groups x 8 d
            int kbk2 = kp >> 3;
            int cc   = kp & 3;
            int wsel = (kp >> 2) & 1;
            const float* va  = vb + (long)(kbase + 2 * kp)     * DHEAD + dgrp * 8;
            const float* vb2 = vb + (long)(kbase + 2 * kp + 1) * DHEAD + dgrp * 8;
            #pragma unroll
            for (int i = 0; i < 2; i++) {
                float4 a  = *(const float4*)(va  + 4 * i);
                float4 b2 = *(const float4*)(vb2 + 4 * i);
                const float xa[4] = {a.x, a.y, a.z, a.w};
                const float xb[4] = {b2.x, b2.y, b2.z, b2.w};
                #pragma unroll
                for (int j = 0; j < 4; j++) {
                    float ha, la, hb, lb;
                    hilo(xa[j], ha, la);
                    hilo(xb[j], hb, lb);
                    int d = dgrp * 8 + 4 * i + j;
                    uint32_t* p = VF + d * VFS + kbk2 * 16 + 4 * cc + wsel;
                    p[0] = packbf2(ha, hb);
                    p[2] = packbf2(la, lb);
                }
            }
        }
        __syncthreads();

        // ---- S = Q @ K^T : 3x bf16 m16n8k16
        float s[4][4];
        #pragma unroll
        for (int j = 0; j < 4; j++)
            #pragma unroll
            for (int i = 0; i < 4; i++) s[j][i] = 0.0f;

        #pragma unroll
        for (int kbk = 0; kbk < 8; kbk++) {
            const uint32_t* qd = QF + (w * 8 + kbk) * 256 + lane * 4;
            uint4 qh = *(const uint4*)qd;
            uint4 ql = *(const uint4*)(qd + 128);
            int rot = kbk >> 1;
            int cs  = 4 * ((c + rot) & 3);   // matches store-side rotation
            #pragma unroll
            for (int j = 0; j < 4; j++) {
                uint4 bw = *(const uint4*)(KF + (8 * j + g) * KFS + kbk * 16 + cs);
                mma_bf16(s[j], qh.x, qh.y, qh.z, qh.w, bw.x, bw.y);
                mma_bf16(s[j], ql.x, ql.y, ql.z, ql.w, bw.x, bw.y);
                mma_bf16(s[j], qh.x, qh.y, qh.z, qh.w, bw.z, bw.w);
            }
        }

        // ---- mask invalid keys
        #pragma unroll
        for (int j = 0; j < 4; j++) {
            int col = kbase + 8 * j + 2 * c;
            if (col     >= vl) { s[j][0] = -3.0e38f; s[j][2] = -3.0e38f; }
            if (col + 1 >= vl) { s[j][1] = -3.0e38f; s[j][3] = -3.0e38f; }
        }

        // ---- online softmax
        float mx0 = -3.0e38f, mx1 = -3.0e38f;
        #pragma unroll
        for (int j = 0; j < 4; j++) {
            mx0 = fmaxf(mx0, fmaxf(s[j][0], s[j][1]));
            mx1 = fmaxf(mx1, fmaxf(s[j][2], s[j][3]));
        }
        mx0 = fmaxf(mx0, __shfl_xor_sync(0xffffffffu, mx0, 1));
        mx0 = fmaxf(mx0, __shfl_xor_sync(0xffffffffu, mx0, 2));
        mx1 = fmaxf(mx1, __shfl_xor_sync(0xffffffffu, mx1, 1));
        mx1 = fmaxf(mx1, __shfl_xor_sync(0xffffffffu, mx1, 2));

        float mn0 = fmaxf(m0, mx0), mn1 = fmaxf(m1, mx1);
        float a0s = __expf(m0 - mn0), a1s = __expf(m1 - mn1);
        m0 = mn0; m1 = mn1;

        float rs0 = 0.0f, rs1 = 0.0f;
        #pragma unroll
        for (int j = 0; j < 4; j++) {
            s[j][0] = __expf(s[j][0] - mn0); rs0 += s[j][0];
            s[j][1] = __expf(s[j][1] - mn0); rs0 += s[j][1];
            s[j][2] = __expf(s[j][2] - mn1); rs1 += s[j][2];
            s[j][3] = __expf(s[j][3] - mn1); rs1 += s[j][3];
        }
        rs0 += __shfl_xor_sync(0xffffffffu, rs0, 1);
        rs0 += __shfl_xor_sync(0xffffffffu, rs0, 2);
        rs1 += __shfl_xor_sync(0xffffffffu, rs1, 1);
        rs1 += __shfl_xor_sync(0xffffffffu, rs1, 2);
        l0s = l0s * a0s + rs0;
        l1s = l1s * a1s + rs1;

        #pragma unroll
        for (int j = 0; j < 16; j++) {
            o[j][0] *= a0s; o[j][1] *= a0s;
            o[j][2] *= a1s; o[j][3] *= a1s;
        }

        // ---- O += P @ V : P in registers
        #pragma unroll
        for (int kbk2 = 0; kbk2 < 2; kbk2++) {
            float h00,lo00,h01,lo01,h02,lo02,h03,lo03;
            float h10,lo10,h11,lo11,h12,lo12,h13,lo13;
            hilo(s[2*kbk2][0], h00, lo00); hilo(s[2*kbk2][1], h01, lo01);
            hilo(s[2*kbk2][2], h02, lo02); hilo(s[2*kbk2][3], h03, lo03);
            hilo(s[2*kbk2+1][0], h10, lo10); hilo(s[2*kbk2+1][1], h11, lo11);
            hilo(s[2*kbk2+1][2], h12, lo12); hilo(s[2*kbk2+1][3], h13, lo13);
            uint32_t ah0 = packbf2(h00, h01),  ah1 = packbf2(h02, h03);
            uint32_t ah2 = packbf2(h10, h11),  ah3 = packbf2(h12, h13);
            uint32_t al0 = packbf2(lo00, lo01), al1 = packbf2(lo02, lo03);
            uint32_t al2 = packbf2(lo10, lo11), al3 = packbf2(lo12, lo13);
            #pragma unroll
            for (int j = 0; j < 16; j++) {
                uint4 bw = *(const uint4*)(VF + (8 * j + g) * VFS + kbk2 * 16 + 4 * c);
                mma_bf16(o[j], ah0, ah1, ah2, ah3, bw.x, bw.y);
                mma_bf16(o[j], al0, al1, al2, al3, bw.x, bw.y);
                mma_bf16(o[j], ah0, ah1, ah2, ah3, bw.z, bw.w);
            }
        }
    }

    // ---- epilogue
    const float i0 = 1.0f / l0s;
    const float i1 = 1.0f / l1s;
    float* or0 = outg + ((long)b * Qlen + r0) * DHEAD;
    float* or1 = outg + ((long)b * Qlen + r1) * DHEAD;
    #pragma unroll
    for (int j = 0; j < 16; j++) {
        *(float2*)(or0 + 8 * j + 2 * c) = make_float2(o[j][0] * i0, o[j][1] * i0);
        *(float2*)(or1 + 8 * j + 2 * c) = make_float2(o[j][2] * i1, o[j][3] * i1);
    }
}

extern "C" void kernel_launch(void* const* d_in, const int* in_sizes, int n_in,
                              void* d_out, int out_size)
{
    const float* q  = (const float*)d_in[0];
    const float* k  = (const float*)d_in[1];
    const float* v  = (const float*)d_in[2];
    const int*   vl = (const int*)d_in[3];

    const int B    = in_sizes[3];
    const int Qlen = in_sizes[0] / (B * DHEAD);
    const int Klen = in_sizes[1] / (B * DHEAD);

    size_t smem = (size_t)SMEM_WORDS * sizeof(uint32_t);   // 108544 B
    cudaFuncSetAttribute(attn_bf16v6_kernel,
                         cudaFuncAttributeMaxDynamicSharedMemorySize, (int)smem);

    dim3 grid(Qlen / BM, B);
    attn_bf16v6_kernel<<<grid, NTH, smem>>>(q, k, v, vl, (float*)d_out, Qlen, Klen);
}

// round 7
// speedup vs baseline: 1.3048x; 1.3048x over previous
#include <cuda_runtime.h>
#include <cuda_bf16.h>
#include <cstdint>
#include <math.h>

#define DHEAD 128
#define BM 128            // q rows per item (8 warps x 16)
#define BN 64             // keys per tile
#define NTH 256
#define NCTAS 256         // persistent CTAs (>= SM count; extras exit instantly)

#define KSTG 132          // fp32 staging stride (floats)
#define KPSTR 68          // Khi/Klo stride (words): conflict-free fragment LDS
#define VPSTR 36          // Vhi/Vlo stride (words): conflict-free fragment LDS

// smem float offsets
#define OFF_KST0 0
#define OFF_VST0 (BN*KSTG)
#define OFF_KST1 (2*BN*KSTG)
#define OFF_VST1 (3*BN*KSTG)
#define OFF_KHI  (4*BN*KSTG)
#define OFF_KLO  (OFF_KHI + BN*KPSTR)
#define OFF_VHI  (OFF_KLO + BN*KPSTR)
#define OFF_VLO  (OFF_VHI + DHEAD*VPSTR)
#define SMEM_FLOATS (OFF_VLO + DHEAD*VPSTR)   // 47744 floats = 190976 B

__device__ unsigned int g_ctr;

__global__ void reset_ctr_kernel() { g_ctr = 0u; }

__device__ __forceinline__ uint32_t packbf2(float x, float y) {
    __nv_bfloat162 t = __floats2bfloat162_rn(x, y);
    return *(uint32_t*)&t;
}
__device__ __forceinline__ void hilo(float x, float& h, float& l) {
    __nv_bfloat16 hb = __float2bfloat16_rn(x);
    h = __bfloat162float(hb);
    l = x - h;
}
__device__ __forceinline__ void mma_bf16(float c[4],
    uint32_t a0, uint32_t a1, uint32_t a2, uint32_t a3,
    uint32_t b0, uint32_t b1)
{
    asm volatile("mma.sync.aligned.m16n8k16.row.col.f32.bf16.bf16.f32 "
        "{%0,%1,%2,%3}, {%4,%5,%6,%7}, {%8,%9}, {%0,%1,%2,%3};"
        : "+f"(c[0]), "+f"(c[1]), "+f"(c[2]), "+f"(c[3])
        : "r"(a0), "r"(a1), "r"(a2), "r"(a3), "r"(b0), "r"(b1));
}
__device__ __forceinline__ void cpasync16(float* dst, const float* src) {
    uint32_t d = (uint32_t)__cvta_generic_to_shared(dst);
    asm volatile("cp.async.cg.shared.global [%0], [%1], 16;" :: "r"(d), "l"(src));
}

__global__ __launch_bounds__(NTH, 1)
void attn_bf16v7_kernel(const float* __restrict__ qg,
                        const float* __restrict__ kg,
                        const float* __restrict__ vg,
                        const int*   __restrict__ vlen,
                        float*       __restrict__ outg,
                        int Qlen, int Klen, int qpb, int nitems)
{
    extern __shared__ float sm[];
    float*    Kst0 = sm + OFF_KST0;
    float*    Vst0 = sm + OFF_VST0;
    uint32_t* Khi = (uint32_t*)(sm + OFF_KHI);
    uint32_t* Klo = (uint32_t*)(sm + OFF_KLO);
    uint32_t* Vhi = (uint32_t*)(sm + OFF_VHI);
    uint32_t* Vlo = (uint32_t*)(sm + OFF_VLO);
    __shared__ unsigned int s_item;

    const int tid  = threadIdx.x;
    const int w    = tid >> 5;
    const int lane = tid & 31;
    const int g    = lane >> 2;
    const int c    = lane & 3;
    const float scale = 0.08838834764831845f;  // 1/sqrt(128)

    for (;;) {
        __syncthreads();                       // prior item fully done (smem safe)
        if (tid == 0) s_item = atomicAdd(&g_ctr, 1u);
        __syncthreads();
        const unsigned int item = s_item;
        if (item >= (unsigned int)nitems) break;

        const int b  = (int)item / qpb;
        const int q0 = ((int)item % qpb) * BM;

        const int vl = vlen[b];
        const int ntiles = (vl + BN - 1) / BN;

        const float* kb = kg + (long)b * Klen * DHEAD;
        const float* vb = vg + (long)b * Klen * DHEAD;

        // ---- Q fragments: hi/lo bf16-packed, pre-scaled
        const int r0 = q0 + 16 * w + g;
        const int r1 = r0 + 8;
        uint32_t qh[8][4], ql[8][4];
        {
            const float* qr0 = qg + ((long)b * Qlen + r0) * DHEAD;
            const float* qr1 = qg + ((long)b * Qlen + r1) * DHEAD;
            #pragma unroll
            for (int kbk = 0; kbk < 8; kbk++) {
                int base = 16 * kbk + 2 * c;
                float h0,l0,h1,l1;
                hilo(qr0[base]     * scale, h0, l0);
                hilo(qr0[base + 1] * scale, h1, l1);
                qh[kbk][0] = packbf2(h0, h1); ql[kbk][0] = packbf2(l0, l1);
                hilo(qr1[base]     * scale, h0, l0);
                hilo(qr1[base + 1] * scale, h1, l1);
                qh[kbk][1] = packbf2(h0, h1); ql[kbk][1] = packbf2(l0, l1);
                hilo(qr0[base + 8] * scale, h0, l0);
                hilo(qr0[base + 9] * scale, h1, l1);
                qh[kbk][2] = packbf2(h0, h1); ql[kbk][2] = packbf2(l0, l1);
                hilo(qr1[base + 8] * scale, h0, l0);
                hilo(qr1[base + 9] * scale, h1, l1);
                qh[kbk][3] = packbf2(h0, h1); ql[kbk][3] = packbf2(l0, l1);
            }
        }

        // ---- prefetch tile 0 into staging buffer 0
        {
            #pragma unroll
            for (int it = 0; it < 8; it++) {
                int idx = tid + it * NTH;
                int row = idx >> 5;
                int c4  = (idx & 31) << 2;
                cpasync16(Kst0 + row * KSTG + c4, kb + (long)row * DHEAD + c4);
                cpasync16(Vst0 + row * KSTG + c4, vb + (long)row * DHEAD + c4);
            }
            asm volatile("cp.async.commit_group;");
        }

        float o[16][4];
        #pragma unroll
        for (int j = 0; j < 16; j++)
            #pragma unroll
            for (int i = 0; i < 4; i++) o[j][i] = 0.0f;
        float m0 = -3.0e38f, m1 = -3.0e38f, l0s = 0.0f, l1s = 0.0f;

        for (int t = 0; t < ntiles; t++) {
            asm volatile("cp.async.wait_group 0;");
            __syncthreads();

            const float* Kst = sm + ((t & 1) ? OFF_KST1 : OFF_KST0);
            const float* Vst = sm + ((t & 1) ? OFF_VST1 : OFF_VST0);

            // ---- convert pass: staging fp32 -> packed bf16 hi/lo
            {
                int key = tid >> 2;
                int q4  = tid & 3;
                #pragma unroll
                for (int i = 0; i < 8; i++) {
                    int d4 = q4 * 8 + i;
                    float4 v = *(const float4*)(Kst + key * KSTG + d4 * 4);
                    float h0,lo0,h1,lo1,h2,lo2,h3,lo3;
                    hilo(v.x, h0, lo0); hilo(v.y, h1, lo1);
                    hilo(v.z, h2, lo2); hilo(v.w, h3, lo3);
                    Khi[key * KPSTR + 2 * d4]     = packbf2(h0, h1);
                    Khi[key * KPSTR + 2 * d4 + 1] = packbf2(h2, h3);
                    Klo[key * KPSTR + 2 * d4]     = packbf2(lo0, lo1);
                    Klo[key * KPSTR + 2 * d4 + 1] = packbf2(lo2, lo3);
                }
                int kp   = tid & 31;
                int dgrp = tid >> 5;
                #pragma unroll
                for (int i = 0; i < 4; i++) {
                    int d4 = dgrp * 4 + i;
                    float4 va = *(const float4*)(Vst + (2 * kp)     * KSTG + d4 * 4);
                    float4 vbv= *(const float4*)(Vst + (2 * kp + 1) * KSTG + d4 * 4);
                    const float xa[4] = {va.x, va.y, va.z, va.w};
                    const float xb[4] = {vbv.x, vbv.y, vbv.z, vbv.w};
                    #pragma unroll
                    for (int j = 0; j < 4; j++) {
                        float ha,la,hb,lb;
                        hilo(xa[j], ha, la);
                        hilo(xb[j], hb, lb);
                        int d = d4 * 4 + j;
                        Vhi[d * VPSTR + kp] = packbf2(ha, hb);
                        Vlo[d * VPSTR + kp] = packbf2(la, lb);
                    }
                }
            }
            __syncthreads();

            // ---- prefetch next tile into the other staging buffer
            if (t + 1 < ntiles) {
                const float* kn = kb + (long)(t + 1) * BN * DHEAD;
                const float* vn = vb + (long)(t + 1) * BN * DHEAD;
                float* Ksn = sm + (((t + 1) & 1) ? OFF_KST1 : OFF_KST0);
                float* Vsn = sm + (((t + 1) & 1) ? OFF_VST1 : OFF_VST0);
                #pragma unroll
                for (int it = 0; it < 8; it++) {
                    int idx = tid + it * NTH;
                    int row = idx >> 5;
                    int c4  = (idx & 31) << 2;
                    cpasync16(Ksn + row * KSTG + c4, kn + (long)row * DHEAD + c4);
                    cpasync16(Vsn + row * KSTG + c4, vn + (long)row * DHEAD + c4);
                }
                asm volatile("cp.async.commit_group;");
            }

            // ---- S = Q @ K^T : 3x bf16 m16n8k16
            float s[8][4];
            #pragma unroll
            for (int j = 0; j < 8; j++)
                #pragma unroll
                for (int i = 0; i < 4; i++) s[j][i] = 0.0f;

            #pragma unroll
            for (int kbk = 0; kbk < 8; kbk++) {
                #pragma unroll
                for (int j = 0; j < 8; j++) {
                    int rowb = (8 * j + g) * KPSTR + 8 * kbk + c;
                    uint32_t bh0 = Khi[rowb];
                    uint32_t bh1 = Khi[rowb + 4];
                    uint32_t bl0 = Klo[rowb];
                    uint32_t bl1 = Klo[rowb + 4];
                    mma_bf16(s[j], qh[kbk][0], qh[kbk][1], qh[kbk][2], qh[kbk][3], bh0, bh1);
                    mma_bf16(s[j], ql[kbk][0], ql[kbk][1], ql[kbk][2], ql[kbk][3], bh0, bh1);
                    mma_bf16(s[j], qh[kbk][0], qh[kbk][1], qh[kbk][2], qh[kbk][3], bl0, bl1);
                }
            }

            // ---- mask invalid keys
            const int kbase = t * BN;
            #pragma unroll
            for (int j = 0; j < 8; j++) {
                int col = kbase + 8 * j + 2 * c;
                if (col     >= vl) { s[j][0] = -3.0e38f; s[j][2] = -3.0e38f; }
                if (col + 1 >= vl) { s[j][1] = -3.0e38f; s[j][3] = -3.0e38f; }
            }

            // ---- online softmax
            float mx0 = -3.0e38f, mx1 = -3.0e38f;
            #pragma unroll
            for (int j = 0; j < 8; j++) {
                mx0 = fmaxf(mx0, fmaxf(s[j][0], s[j][1]));
                mx1 = fmaxf(mx1, fmaxf(s[j][2], s[j][3]));
            }
            mx0 = fmaxf(mx0, __shfl_xor_sync(0xffffffffu, mx0, 1));
            mx0 = fmaxf(mx0, __shfl_xor_sync(0xffffffffu, mx0, 2));
            mx1 = fmaxf(mx1, __shfl_xor_sync(0xffffffffu, mx1, 1));
            mx1 = fmaxf(mx1, __shfl_xor_sync(0xffffffffu, mx1, 2));

            float mn0 = fmaxf(m0, mx0), mn1 = fmaxf(m1, mx1);
            float a0s = __expf(m0 - mn0), a1s = __expf(m1 - mn1);
            m0 = mn0; m1 = mn1;

            float rs0 = 0.0f, rs1 = 0.0f;
            #pragma unroll
            for (int j = 0; j < 8; j++) {
                s[j][0] = __expf(s[j][0] - mn0); rs0 += s[j][0];
                s[j][1] = __expf(s[j][1] - mn0); rs0 += s[j][1];
                s[j][2] = __expf(s[j][2] - mn1); rs1 += s[j][2];
                s[j][3] = __expf(s[j][3] - mn1); rs1 += s[j][3];
            }
            rs0 += __shfl_xor_sync(0xffffffffu, rs0, 1);
            rs0 += __shfl_xor_sync(0xffffffffu, rs0, 2);
            rs1 += __shfl_xor_sync(0xffffffffu, rs1, 1);
            rs1 += __shfl_xor_sync(0xffffffffu, rs1, 2);
            l0s = l0s * a0s + rs0;
            l1s = l1s * a1s + rs1;

            #pragma unroll
            for (int j = 0; j < 16; j++) {
                o[j][0] *= a0s; o[j][1] *= a0s;
                o[j][2] *= a1s; o[j][3] *= a1s;
            }

            // ---- O += P @ V : P in registers
            #pragma unroll
            for (int kbk = 0; kbk < 4; kbk++) {
                float h00,lo00,h01,lo01,h02,lo02,h03,lo03;
                float h10,lo10,h11,lo11,h12,lo12,h13,lo13;
                hilo(s[2*kbk][0], h00, lo00); hilo(s[2*kbk][1], h01, lo01);
                hilo(s[2*kbk][2], h02, lo02); hilo(s[2*kbk][3], h03, lo03);
                hilo(s[2*kbk+1][0], h10, lo10); hilo(s[2*kbk+1][1], h11, lo11);
                hilo(s[2*kbk+1][2], h12, lo12); hilo(s[2*kbk+1][3], h13, lo13);
                uint32_t ah0 = packbf2(h00, h01),  ah1 = packbf2(h02, h03);
                uint32_t ah2 = packbf2(h10, h11),  ah3 = packbf2(h12, h13);
                uint32_t al0 = packbf2(lo00, lo01), al1 = packbf2(lo02, lo03);
                uint32_t al2 = packbf2(lo10, lo11), al3 = packbf2(lo12, lo13);
                #pragma unroll
                for (int j = 0; j < 16; j++) {
                    int rowb = (8 * j + g) * VPSTR + 8 * kbk + c;
                    uint32_t bh0 = Vhi[rowb];
                    uint32_t bh1 = Vhi[rowb + 4];
                    uint32_t bl0 = Vlo[rowb];
                    uint32_t bl1 = Vlo[rowb + 4];
                    mma_bf16(o[j], ah0, ah1, ah2, ah3, bh0, bh1);
                    mma_bf16(o[j], al0, al1, al2, al3, bh0, bh1);
                    mma_bf16(o[j], ah0, ah1, ah2, ah3, bl0, bl1);
                }
            }
        }

        // ---- epilogue
        const float i0 = 1.0f / l0s;
        const float i1 = 1.0f / l1s;
        float* or0 = outg + ((long)b * Qlen + r0) * DHEAD;
        float* or1 = outg + ((long)b * Qlen + r1) * DHEAD;
        #pragma unroll
        for (int j = 0; j < 16; j++) {
            *(float2*)(or0 + 8 * j + 2 * c) = make_float2(o[j][0] * i0, o[j][1] * i0);
            *(float2*)(or1 + 8 * j + 2 * c) = make_float2(o[j][2] * i1, o[j][3] * i1);
        }
    }
}

extern "C" void kernel_launch(void* const* d_in, const int* in_sizes, int n_in,
                              void* d_out, int out_size)
{
    const float* q  = (const float*)d_in[0];
    const float* k  = (const float*)d_in[1];
    const float* v  = (const float*)d_in[2];
    const int*   vl = (const int*)d_in[3];

    const int B    = in_sizes[3];
    const int Qlen = in_sizes[0] / (B * DHEAD);
    const int Klen = in_sizes[1] / (B * DHEAD);
    const int qpb  = Qlen / BM;
    const int nitems = B * qpb;

    size_t smem = (size_t)SMEM_FLOATS * sizeof(float);
    cudaFuncSetAttribute(attn_bf16v7_kernel,
                         cudaFuncAttributeMaxDynamicSharedMemorySize, (int)smem);

    reset_ctr_kernel<<<1, 1>>>();
    attn_bf16v7_kernel<<<NCTAS, NTH, smem>>>(q, k, v, vl, (float*)d_out,
                                             Qlen, Klen, qpb, nitems);
}

// round 9
// speedup vs baseline: 1.3221x; 1.0133x over previous
#include <cuda_runtime.h>
#include <cuda_bf16.h>
#include <cstdint>
#include <math.h>

#define DHEAD 128
#define BM 128            // q rows per item (8 warps x 16)
#define BN 64             // keys per tile
#define NTH 256
#define NCTAS 256         // persistent CTAs

#define KSTG 132          // fp32 staging stride (floats)
#define KPSTR 68          // Khi/Klo stride (words)
#define VPSTR 36          // Vhi/Vlo stride (words)

// smem float offsets
#define OFF_KST0 0
#define OFF_VST0 (BN*KSTG)
#define OFF_KST1 (2*BN*KSTG)
#define OFF_VST1 (3*BN*KSTG)
#define OFF_KHI  (4*BN*KSTG)
#define OFF_KLO  (OFF_KHI + BN*KPSTR)
#define OFF_VHI  (OFF_KLO + BN*KPSTR)
#define OFF_VLO  (OFF_VHI + DHEAD*VPSTR)
#define SMEM_FLOATS (OFF_VLO + DHEAD*VPSTR)   // 47744 floats = 190976 B

__device__ unsigned int g_ctr;
__global__ void reset_ctr_kernel() { g_ctr = 0u; }

__device__ __forceinline__ uint32_t packbf2(float x, float y) {
    __nv_bfloat162 t = __floats2bfloat162_rn(x, y);
    return *(uint32_t*)&t;
}
__device__ __forceinline__ void hilo(float x, float& h, float& l) {
    __nv_bfloat16 hb = __float2bfloat16_rn(x);
    h = __bfloat162float(hb);
    l = x - h;
}
__device__ __forceinline__ void mma_bf16(float c[4],
    uint32_t a0, uint32_t a1, uint32_t a2, uint32_t a3,
    uint32_t b0, uint32_t b1)
{
    asm volatile("mma.sync.aligned.m16n8k16.row.col.f32.bf16.bf16.f32 "
        "{%0,%1,%2,%3}, {%4,%5,%6,%7}, {%8,%9}, {%0,%1,%2,%3};"
        : "+f"(c[0]), "+f"(c[1]), "+f"(c[2]), "+f"(c[3])
        : "r"(a0), "r"(a1), "r"(a2), "r"(a3), "r"(b0), "r"(b1));
}
__device__ __forceinline__ void cpasync16(float* dst, const float* src) {
    uint32_t d = (uint32_t)__cvta_generic_to_shared(dst);
    asm volatile("cp.async.cg.shared.global [%0], [%1], 16;" :: "r"(d), "l"(src));
}

__global__ __launch_bounds__(NTH, 1)
void attn_bf16v8_kernel(const float* __restrict__ qg,
                        const float* __restrict__ kg,
                        const float* __restrict__ vg,
                        const int*   __restrict__ vlen,
                        float*       __restrict__ outg,
                        int Qlen, int Klen, int qpb, int nitems)
{
    extern __shared__ float sm[];
    float*    Kst0 = sm + OFF_KST0;
    float*    Vst0 = sm + OFF_VST0;
    uint32_t* Khi = (uint32_t*)(sm + OFF_KHI);
    uint32_t* Klo = (uint32_t*)(sm + OFF_KLO);
    uint32_t* Vhi = (uint32_t*)(sm + OFF_VHI);
    uint32_t* Vlo = (uint32_t*)(sm + OFF_VLO);
    __shared__ unsigned int s_item;

    const int tid  = threadIdx.x;
    const int w    = tid >> 5;
    const int lane = tid & 31;
    const int g    = lane >> 2;
    const int c    = lane & 3;
    const float scale = 0.08838834764831845f;  // 1/sqrt(128)

    for (;;) {
        __syncthreads();
        if (tid == 0) s_item = atomicAdd(&g_ctr, 1u);
        __syncthreads();
        const unsigned int item = s_item;
        if (item >= (unsigned int)nitems) break;

        const int b  = (int)item / qpb;
        const int q0 = ((int)item % qpb) * BM;

        const int vl = vlen[b];
        const int ntiles = (vl + BN - 1) / BN;

        const float* kb = kg + (long)b * Klen * DHEAD;
        const float* vb = vg + (long)b * Klen * DHEAD;

        // ---- Q fragments: hi/lo bf16-packed, pre-scaled
        const int r0 = q0 + 16 * w + g;
        const int r1 = r0 + 8;
        uint32_t qh[8][4], ql[8][4];
        {
            const float* qr0 = qg + ((long)b * Qlen + r0) * DHEAD;
            const float* qr1 = qg + ((long)b * Qlen + r1) * DHEAD;
            #pragma unroll
            for (int kbk = 0; kbk < 8; kbk++) {
                int base = 16 * kbk + 2 * c;
                float h0,l0,h1,l1;
                hilo(qr0[base]     * scale, h0, l0);
                hilo(qr0[base + 1] * scale, h1, l1);
                qh[kbk][0] = packbf2(h0, h1); ql[kbk][0] = packbf2(l0, l1);
                hilo(qr1[base]     * scale, h0, l0);
                hilo(qr1[base + 1] * scale, h1, l1);
                qh[kbk][1] = packbf2(h0, h1); ql[kbk][1] = packbf2(l0, l1);
                hilo(qr0[base + 8] * scale, h0, l0);
                hilo(qr0[base + 9] * scale, h1, l1);
                qh[kbk][2] = packbf2(h0, h1); ql[kbk][2] = packbf2(l0, l1);
                hilo(qr1[base + 8] * scale, h0, l0);
                hilo(qr1[base + 9] * scale, h1, l1);
                qh[kbk][3] = packbf2(h0, h1); ql[kbk][3] = packbf2(l0, l1);
            }
        }

        // ---- prefetch tile 0 into staging buffer 0
        {
            #pragma unroll
            for (int it = 0; it < 8; it++) {
                int idx = tid + it * NTH;
                int row = idx >> 5;
                int c4  = (idx & 31) << 2;
                cpasync16(Kst0 + row * KSTG + c4, kb + (long)row * DHEAD + c4);
                cpasync16(Vst0 + row * KSTG + c4, vb + (long)row * DHEAD + c4);
            }
            asm volatile("cp.async.commit_group;");
        }

        float o[16][4];
        #pragma unroll
        for (int j = 0; j < 16; j++)
            #pragma unroll
            for (int i = 0; i < 4; i++) o[j][i] = 0.0f;
        float m0 = -3.0e38f, m1 = -3.0e38f, l0s = 0.0f, l1s = 0.0f;

        for (int t = 0; t < ntiles; t++) {
            asm volatile("cp.async.wait_group 0;");
            __syncthreads();

            const float* Kst = sm + ((t & 1) ? OFF_KST1 : OFF_KST0);
            const float* Vst = sm + ((t & 1) ? OFF_VST1 : OFF_VST0);

            // ---- convert pass: staging fp32 -> packed bf16 hi/lo
            {
                int key = tid >> 2;
                int q4  = tid & 3;
                #pragma unroll
                for (int i = 0; i < 8; i++) {
                    int d4 = q4 * 8 + i;
                    float4 v = *(const float4*)(Kst + key * KSTG + d4 * 4);
                    float h0,lo0,h1,lo1,h2,lo2,h3,lo3;
                    hilo(v.x, h0, lo0); hilo(v.y, h1, lo1);
                    hilo(v.z, h2, lo2); hilo(v.w, h3, lo3);
                    Khi[key * KPSTR + 2 * d4]     = packbf2(h0, h1);
                    Khi[key * KPSTR + 2 * d4 + 1] = packbf2(h2, h3);
                    Klo[key * KPSTR + 2 * d4]     = packbf2(lo0, lo1);
                    Klo[key * KPSTR + 2 * d4 + 1] = packbf2(lo2, lo3);
                }
                int kp   = tid & 31;
                int dgrp = tid >> 5;
                #pragma unroll
                for (int i = 0; i < 4; i++) {
                    int d4 = dgrp * 4 + i;
                    float4 va = *(const float4*)(Vst + (2 * kp)     * KSTG + d4 * 4);
                    float4 vbv= *(const float4*)(Vst + (2 * kp + 1) * KSTG + d4 * 4);
                    const float xa[4] = {va.x, va.y, va.z, va.w};
                    const float xb[4] = {vbv.x, vbv.y, vbv.z, vbv.w};
                    #pragma unroll
                    for (int j = 0; j < 4; j++) {
                        float ha,la,hb,lb;
                        hilo(xa[j], ha, la);
                        hilo(xb[j], hb, lb);
                        int d = d4 * 4 + j;
                        Vhi[d * VPSTR + kp] = packbf2(ha, hb);
                        Vlo[d * VPSTR + kp] = packbf2(la, lb);
                    }
                }
            }
            __syncthreads();

            // ---- prefetch next tile into the other staging buffer
            if (t + 1 < ntiles) {
                const float* kn = kb + (long)(t + 1) * BN * DHEAD;
                const float* vn = vb + (long)(t + 1) * BN * DHEAD;
                float* Ksn = sm + (((t + 1) & 1) ? OFF_KST1 : OFF_KST0);
                float* Vsn = sm + (((t + 1) & 1) ? OFF_VST1 : OFF_VST0);
                #pragma unroll
                for (int it = 0; it < 8; it++) {
                    int idx = tid + it * NTH;
                    int row = idx >> 5;
                    int c4  = (idx & 31) << 2;
                    cpasync16(Ksn + row * KSTG + c4, kn + (long)row * DHEAD + c4);
                    cpasync16(Vsn + row * KSTG + c4, vn + (long)row * DHEAD + c4);
                }
                asm volatile("cp.async.commit_group;");
            }

            // ---- S = Q @ K^T : term-outer / j-inner (accumulator distance 8)
            float s[8][4];
            #pragma unroll
            for (int j = 0; j < 8; j++)
                #pragma unroll
                for (int i = 0; i < 4; i++) s[j][i] = 0.0f;

            #pragma unroll
            for (int kbk = 0; kbk < 8; kbk++) {
                // term 0: qh x Khi
                #pragma unroll
                for (int j = 0; j < 8; j++) {
                    int rowb = (8 * j + g) * KPSTR + 8 * kbk + c;
                    mma_bf16(s[j], qh[kbk][0], qh[kbk][1], qh[kbk][2], qh[kbk][3],
                             Khi[rowb], Khi[rowb + 4]);
                }
                // term 1: ql x Khi
                #pragma unroll
                for (int j = 0; j < 8; j++) {
                    int rowb = (8 * j + g) * KPSTR + 8 * kbk + c;
                    mma_bf16(s[j], ql[kbk][0], ql[kbk][1], ql[kbk][2], ql[kbk][3],
                             Khi[rowb], Khi[rowb + 4]);
                }
                // term 2: qh x Klo
                #pragma unroll
                for (int j = 0; j < 8; j++) {
                    int rowb = (8 * j + g) * KPSTR + 8 * kbk + c;
                    mma_bf16(s[j], qh[kbk][0], qh[kbk][1], qh[kbk][2], qh[kbk][3],
                             Klo[rowb], Klo[rowb + 4]);
                }
            }

            // ---- mask invalid keys
            const int kbase = t * BN;
            #pragma unroll
            for (int j = 0; j < 8; j++) {
                int col = kbase + 8 * j + 2 * c;
                if (col     >= vl) { s[j][0] = -3.0e38f; s[j][2] = -3.0e38f; }
                if (col + 1 >= vl) { s[j][1] = -3.0e38f; s[j][3] = -3.0e38f; }
            }

            // ---- online softmax
            float mx0 = -3.0e38f, mx1 = -3.0e38f;
            #pragma unroll
            for (int j = 0; j < 8; j++) {
                mx0 = fmaxf(mx0, fmaxf(s[j][0], s[j][1]));
                mx1 = fmaxf(mx1, fmaxf(s[j][2], s[j][3]));
            }
            mx0 = fmaxf(mx0, __shfl_xor_sync(0xffffffffu, mx0, 1));
            mx0 = fmaxf(mx0, __shfl_xor_sync(0xffffffffu, mx0, 2));
            mx1 = fmaxf(mx1, __shfl_xor_sync(0xffffffffu, mx1, 1));
            mx1 = fmaxf(mx1, __shfl_xor_sync(0xffffffffu, mx1, 2));

            float mn0 = fmaxf(m0, mx0), mn1 = fmaxf(m1, mx1);
            float a0s = __expf(m0 - mn0), a1s = __expf(m1 - mn1);
            m0 = mn0; m1 = mn1;

            float rs0 = 0.0f, rs1 = 0.0f;
            #pragma unroll
            for (int j = 0; j < 8; j++) {
                s[j][0] = __expf(s[j][0] - mn0); rs0 += s[j][0];
                s[j][1] = __expf(s[j][1] - mn0); rs0 += s[j][1];
                s[j][2] = __expf(s[j][2] - mn1); rs1 += s[j][2];
                s[j][3] = __expf(s[j][3] - mn1); rs1 += s[j][3];
            }
            rs0 += __shfl_xor_sync(0xffffffffu, rs0, 1);
            rs0 += __shfl_xor_sync(0xffffffffu, rs0, 2);
            rs1 += __shfl_xor_sync(0xffffffffu, rs1, 1);
            rs1 += __shfl_xor_sync(0xffffffffu, rs1, 2);
            l0s = l0s * a0s + rs0;
            l1s = l1s * a1s + rs1;

            #pragma unroll
            for (int j = 0; j < 16; j++) {
                o[j][0] *= a0s; o[j][1] *= a0s;
                o[j][2] *= a1s; o[j][3] *= a1s;
            }

            // ---- precompute ALL P hi/lo fragments (registers), then PV
            uint32_t pah[4][4], pal[4][4];
            #pragma unroll
            for (int kbk = 0; kbk < 4; kbk++) {
                float h00,lo00,h01,lo01,h02,lo02,h03,lo03;
                float h10,lo10,h11,lo11,h12,lo12,h13,lo13;
                hilo(s[2*kbk][0], h00, lo00); hilo(s[2*kbk][1], h01, lo01);
                hilo(s[2*kbk][2], h02, lo02); hilo(s[2*kbk][3], h03, lo03);
                hilo(s[2*kbk+1][0], h10, lo10); hilo(s[2*kbk+1][1], h11, lo11);
                hilo(s[2*kbk+1][2], h12, lo12); hilo(s[2*kbk+1][3], h13, lo13);
                pah[kbk][0] = packbf2(h00, h01);  pah[kbk][1] = packbf2(h02, h03);
                pah[kbk][2] = packbf2(h10, h11);  pah[kbk][3] = packbf2(h12, h13);
                pal[kbk][0] = packbf2(lo00, lo01); pal[kbk][1] = packbf2(lo02, lo03);
                pal[kbk][2] = packbf2(lo10, lo11); pal[kbk][3] = packbf2(lo12, lo13);
            }

            // O += P @ V : term-outer / j-inner (accumulator distance 16)
            #pragma unroll
            for (int kbk = 0; kbk < 4; kbk++) {
                // term 0: Phi x Vhi
                #pragma unroll
                for (int j = 0; j < 16; j++) {
                    int rowb = (8 * j + g) * VPSTR + 8 * kbk + c;
                    mma_bf16(o[j], pah[kbk][0], pah[kbk][1], pah[kbk][2], pah[kbk][3],
                             Vhi[rowb], Vhi[rowb + 4]);
                }
                // term 1: Plo x Vhi
                #pragma unroll
                for (int j = 0; j < 16; j++) {
                    int rowb = (8 * j + g) * VPSTR + 8 * kbk + c;
                    mma_bf16(o[j], pal[kbk][0], pal[kbk][1], pal[kbk][2], pal[kbk][3],
                             Vhi[rowb], Vhi[rowb + 4]);
                }
                // term 2: Phi x Vlo
                #pragma unroll
                for (int j = 0; j < 16; j++) {
                    int rowb = (8 * j + g) * VPSTR + 8 * kbk + c;
                    mma_bf16(o[j], pah[kbk][0], pah[kbk][1], pah[kbk][2], pah[kbk][3],
                             Vlo[rowb], Vlo[rowb + 4]);
                }
            }
        }

        // ---- epilogue
        const float i0 = 1.0f / l0s;
        const float i1 = 1.0f / l1s;
        float* or0 = outg + ((long)b * Qlen + r0) * DHEAD;
        float* or1 = outg + ((long)b * Qlen + r1) * DHEAD;
        #pragma unroll
        for (int j = 0; j < 16; j++) {
            *(float2*)(or0 + 8 * j + 2 * c) = make_float2(o[j][0] * i0, o[j][1] * i0);
            *(float2*)(or1 + 8 * j + 2 * c) = make_float2(o[j][2] * i1, o[j][3] * i1);
        }
    }
}

extern "C" void kernel_launch(void* const* d_in, const int* in_sizes, int n_in,
                              void* d_out, int out_size)
{
    const float* q  = (const float*)d_in[0];
    const float* k  = (const float*)d_in[1];
    const float* v  = (const float*)d_in[2];
    const int*   vl = (const int*)d_in[3];

    const int B    = in_sizes[3];
    const int Qlen = in_sizes[0] / (B * DHEAD);
    const int Klen = in_sizes[1] / (B * DHEAD);
    const int qpb  = Qlen / BM;
    const int nitems = B * qpb;

    size_t smem = (size_t)SMEM_FLOATS * sizeof(float);
    cudaFuncSetAttribute(attn_bf16v8_kernel,
                         cudaFuncAttributeMaxDynamicSharedMemorySize, (int)smem);

    reset_ctr_kernel<<<1, 1>>>();
    attn_bf16v8_kernel<<<NCTAS, NTH, smem>>>(q, k, v, vl, (float*)d_out,
                                             Qlen, Klen, qpb, nitems);
}